// round 10
// baseline (speedup 1.0000x reference)
#include <cuda_runtime.h>
#include <cstdint>

// ---------------------------------------------------------------------------
// DoubleAttention, restructured (A-conv algebraically eliminated):
//   L = [wB;wV] x + [bB;bV]     (2x GEMM  M=512, N=4096, K=512, per batch)
//   Bm, av = softmax_rows(L)
//   S  = Bm @ x^T               (GEMM M=512, N=512, K=4096; split-K=4 + reduce)
//   gd = S @ wA^T * 1/HW + bA/HW
//   out= gd^T @ av              (GEMM M=512, N=4096, K=512)
// tf32 tensor cores, fp32 accumulate, cvt.rna at SMEM-store time.
// Block tile 128x256, 256 threads = 8 warps of 64x64 (LDS:mma = 1.0) --
// 2 warps/SMSP for latency hiding (fixes round-9's occ=11%, 1 warp/SMSP).
// XOR-swizzled k-major SMEM, all access paths bank-conflict-free.
// Main loop unrolled by 2 so buffer indices are compile-time.
// ---------------------------------------------------------------------------

#define BB   8
#define CC   512
#define HW_  4096

#define BM 128
#define BN 256
#define BK 16
#define PAD 8          // row strides 136/264 words: both = 8 mod 32

#define NSPLIT4 4

// Scratch (__device__ globals; allocation is forbidden)
__device__ float g_logits[BB * 2 * CC * HW_];          // 134MB
__device__ float g_Sp[NSPLIT4 * BB * CC * CC];         // 33.5MB split-K partials
__device__ float g_S [BB * CC * CC];                   // 8MB
__device__ float g_gd[BB * CC * CC];                   // 8MB

__device__ __forceinline__ uint32_t f2tf(float f) {
    uint32_t u;
    asm("cvt.rna.tf32.f32 %0, %1;" : "=r"(u) : "f"(f));
    return u;
}

__device__ __forceinline__ void mma8(float* c, const uint32_t* a, const uint32_t* b) {
    asm volatile(
        "mma.sync.aligned.m16n8k8.row.col.f32.tf32.tf32.f32 "
        "{%0,%1,%2,%3},{%4,%5,%6,%7},{%8,%9},{%0,%1,%2,%3};"
        : "+f"(c[0]), "+f"(c[1]), "+f"(c[2]), "+f"(c[3])
        : "r"(a[0]), "r"(a[1]), "r"(a[2]), "r"(a[3]), "r"(b[0]), "r"(b[1]));
}

// XOR swizzle: inject k bits 2..3 into column bank bits 3..4.
__device__ __forceinline__ int swz(int col, int k) {
    return col ^ (((k >> 2) & 3) << 3);
}

// D[m,n] = scale * sum_k A[m,k]*B[k,n]  (+ biasScale*bias[row or col])
// TA: A stored [K,M] row-major; else [M,K].  TB: B stored [N,K]; else [K,N].
// NSPLIT: split-K factor; partial sp is written at D + sp*sSplit.
template <bool TA, bool TB, int NSPLIT>
__global__ __launch_bounds__(256, 1) void gemm_tf32(
    const float* __restrict__ Abase, const float* __restrict__ Bbase,
    float* __restrict__ Dbase, int M, int N, int K,
    long sA, long sB, long sD, long sSplit,
    const float* __restrict__ bias, int biasMode, float scale, float biasScale)
{
    // k-major swizzled tiles holding tf32 bit patterns.
    __shared__ uint32_t As[2][BK][BM + PAD];   // 17.4KB
    __shared__ uint32_t Bs[2][BK][BN + PAD];   // 33.8KB

    const int bz    = blockIdx.z;
    const int batch = bz / NSPLIT;
    const int sp    = bz % NSPLIT;
    const int Kl    = K / NSPLIT;
    const int koff  = sp * Kl;

    const float* A  = Abase + (long)batch * sA;
    const float* Bp = Bbase + (long)batch * sB;
    float* D        = Dbase + (long)batch * sD + (long)sp * sSplit;

    const int bm   = blockIdx.y * BM;
    const int bn   = blockIdx.x * BN;
    const int tid  = threadIdx.x;
    const int lane = tid & 31;
    const int warp = tid >> 5;
    const int m0   = (warp & 1) * 64;   // 2 warps along M
    const int n0   = (warp >> 1) * 64;  // 4 warps along N
    const int r    = lane >> 2;         // 0..7
    const int cg   = lane & 3;          // 0..3

    float acc[4][8][4];
#pragma unroll
    for (int i = 0; i < 4; i++)
#pragma unroll
        for (int j = 0; j < 8; j++)
#pragma unroll
            for (int k = 0; k < 4; k++) acc[i][j][k] = 0.f;

    float4 pa[2], pb[4];

    auto loadA = [&](int k0) {
#pragma unroll
        for (int i = 0; i < 2; i++) {
            int idx = tid + i * 256;  // 512 float4 per tile (128x16)
            if (!TA) {
                int m = idx >> 2, kq = idx & 3;
                pa[i] = *reinterpret_cast<const float4*>(&A[(long)(bm + m) * K + k0 + kq * 4]);
            } else {
                int k = idx >> 5, mq = idx & 31;
                pa[i] = *reinterpret_cast<const float4*>(&A[(long)(k0 + k) * M + bm + mq * 4]);
            }
        }
    };
    auto storeA = [&](uint32_t (*Asb)[BM + PAD]) {
#pragma unroll
        for (int i = 0; i < 2; i++) {
            int idx = tid + i * 256;
            if (!TA) {  // transpose into k-major smem; swizzle kills kq-collisions
                int m = idx >> 2, kq = idx & 3;
                Asb[kq * 4 + 0][swz(m, kq * 4 + 0)] = f2tf(pa[i].x);
                Asb[kq * 4 + 1][swz(m, kq * 4 + 1)] = f2tf(pa[i].y);
                Asb[kq * 4 + 2][swz(m, kq * 4 + 2)] = f2tf(pa[i].z);
                Asb[kq * 4 + 3][swz(m, kq * 4 + 3)] = f2tf(pa[i].w);
            } else {    // direct: convert then one STS.128
                int k = idx >> 5, mq = idx & 31;
                uint4 v = {f2tf(pa[i].x), f2tf(pa[i].y), f2tf(pa[i].z), f2tf(pa[i].w)};
                *reinterpret_cast<uint4*>(&Asb[k][swz(mq * 4, k)]) = v;
            }
        }
    };
    auto loadB = [&](int k0) {
#pragma unroll
        for (int i = 0; i < 4; i++) {
            int idx = tid + i * 256;  // 1024 float4 per tile (16x256)
            if (!TB) {
                int k = idx >> 6, nq = idx & 63;
                pb[i] = *reinterpret_cast<const float4*>(&Bp[(long)(k0 + k) * N + bn + nq * 4]);
            } else {
                int n = idx >> 2, kq = idx & 3;
                pb[i] = *reinterpret_cast<const float4*>(&Bp[(long)(bn + n) * K + k0 + kq * 4]);
            }
        }
    };
    auto storeB = [&](uint32_t (*Bsb)[BN + PAD]) {
#pragma unroll
        for (int i = 0; i < 4; i++) {
            int idx = tid + i * 256;
            if (!TB) {
                int k = idx >> 6, nq = idx & 63;
                uint4 v = {f2tf(pb[i].x), f2tf(pb[i].y), f2tf(pb[i].z), f2tf(pb[i].w)};
                *reinterpret_cast<uint4*>(&Bsb[k][swz(nq * 4, k)]) = v;
            } else {    // transpose into k-major smem
                int n = idx >> 2, kq = idx & 3;
                Bsb[kq * 4 + 0][swz(n, kq * 4 + 0)] = f2tf(pb[i].x);
                Bsb[kq * 4 + 1][swz(n, kq * 4 + 1)] = f2tf(pb[i].y);
                Bsb[kq * 4 + 2][swz(n, kq * 4 + 2)] = f2tf(pb[i].z);
                Bsb[kq * 4 + 3][swz(n, kq * 4 + 3)] = f2tf(pb[i].w);
            }
        }
    };

    // Compute on one (compile-time) buffer: all LDS addresses are
    // base-register + immediate after inlining.
    auto compute = [&](const uint32_t (*Asb)[BM + PAD],
                       const uint32_t (*Bsb)[BN + PAD]) {
#pragma unroll
        for (int kk = 0; kk < BK; kk += 8) {
            const int kA = kk + cg;       // rows used by this thread's fragments
            const int kB = kk + cg + 4;
            const int c0 = ((kA >> 2) & 3) << 3;
            const int c1 = ((kB >> 2) & 3) << 3;
            uint32_t afr[4][4], bfr[8][2];
#pragma unroll
            for (int mt = 0; mt < 4; mt++) {
                int mrow = m0 + mt * 16;
                afr[mt][0] = Asb[kA][(mrow + r)     ^ c0];
                afr[mt][1] = Asb[kA][(mrow + r + 8) ^ c0];
                afr[mt][2] = Asb[kB][(mrow + r)     ^ c1];
                afr[mt][3] = Asb[kB][(mrow + r + 8) ^ c1];
            }
#pragma unroll
            for (int nt = 0; nt < 8; nt++) {
                int ncol = n0 + nt * 8 + r;
                bfr[nt][0] = Bsb[kA][ncol ^ c0];
                bfr[nt][1] = Bsb[kB][ncol ^ c1];
            }
#pragma unroll
            for (int mt = 0; mt < 4; mt++)
#pragma unroll
                for (int nt = 0; nt < 8; nt++) mma8(acc[mt][nt], afr[mt], bfr[nt]);
        }
    };

    const int nk = Kl / BK;   // always even (>= 32) for this problem
    loadA(koff); loadB(koff);
    storeA(As[0]); storeB(Bs[0]);
    __syncthreads();

    for (int kt = 0; kt < nk; kt += 2) {
        // half-iteration 0: compute buf0, fill buf1 (kt+1 < nk always: nk even)
        loadA(koff + (kt + 1) * BK); loadB(koff + (kt + 1) * BK);
        compute(As[0], Bs[0]);
        storeA(As[1]); storeB(Bs[1]);
        __syncthreads();
        // half-iteration 1: compute buf1, fill buf0
        const bool more = (kt + 2 < nk);
        if (more) { loadA(koff + (kt + 2) * BK); loadB(koff + (kt + 2) * BK); }
        compute(As[1], Bs[1]);
        if (more) {
            storeA(As[0]); storeB(Bs[0]);
            __syncthreads();
        }
    }

    // epilogue
#pragma unroll
    for (int mt = 0; mt < 4; mt++) {
        int row0 = bm + m0 + mt * 16 + r;
#pragma unroll
        for (int nt = 0; nt < 8; nt++) {
            int col = bn + n0 + nt * 8 + cg * 2;
            float v0 = acc[mt][nt][0] * scale;
            float v1 = acc[mt][nt][1] * scale;
            float v2 = acc[mt][nt][2] * scale;
            float v3 = acc[mt][nt][3] * scale;
            if (biasMode == 1) {
                float b0 = bias[row0] * biasScale;
                float b1 = bias[row0 + 8] * biasScale;
                v0 += b0; v1 += b0; v2 += b1; v3 += b1;
            } else if (biasMode == 2) {
                float b0 = bias[col] * biasScale;
                float b1 = bias[col + 1] * biasScale;
                v0 += b0; v1 += b1; v2 += b0; v3 += b1;
            }
            D[(long)row0 * N + col]           = v0;
            D[(long)row0 * N + col + 1]       = v1;
            D[(long)(row0 + 8) * N + col]     = v2;
            D[(long)(row0 + 8) * N + col + 1] = v3;
        }
    }
}

// In-place softmax over rows of length 4096. One CTA (256 threads) per row.
__global__ __launch_bounds__(256, 1) void softmax_rows(float* __restrict__ buf) {
    float* p = buf + (long)blockIdx.x * HW_;
    const int tid  = threadIdx.x;
    const int lane = tid & 31;
    const int warp = tid >> 5;
    __shared__ float red[8];

    float4 v[4];
    float4* p4 = reinterpret_cast<float4*>(p);
#pragma unroll
    for (int i = 0; i < 4; i++) v[i] = p4[i * 256 + tid];

    float mx = v[0].x;
#pragma unroll
    for (int i = 0; i < 4; i++) {
        mx = fmaxf(mx, v[i].x); mx = fmaxf(mx, v[i].y);
        mx = fmaxf(mx, v[i].z); mx = fmaxf(mx, v[i].w);
    }
#pragma unroll
    for (int o = 16; o; o >>= 1) mx = fmaxf(mx, __shfl_xor_sync(0xffffffffu, mx, o));
    if (lane == 0) red[warp] = mx;
    __syncthreads();
    mx = red[0];
#pragma unroll
    for (int w = 1; w < 8; w++) mx = fmaxf(mx, red[w]);
    __syncthreads();

    float s = 0.f;
#pragma unroll
    for (int i = 0; i < 4; i++) {
        v[i].x = __expf(v[i].x - mx); s += v[i].x;
        v[i].y = __expf(v[i].y - mx); s += v[i].y;
        v[i].z = __expf(v[i].z - mx); s += v[i].z;
        v[i].w = __expf(v[i].w - mx); s += v[i].w;
    }
#pragma unroll
    for (int o = 16; o; o >>= 1) s += __shfl_xor_sync(0xffffffffu, s, o);
    if (lane == 0) red[warp] = s;
    __syncthreads();
    s = 0.f;
#pragma unroll
    for (int w = 0; w < 8; w++) s += red[w];
    const float inv = 1.f / s;
#pragma unroll
    for (int i = 0; i < 4; i++) {
        v[i].x *= inv; v[i].y *= inv; v[i].z *= inv; v[i].w *= inv;
        p4[i * 256 + tid] = v[i];
    }
}

// S = (p0 + p1 + p2 + p3) * scale   (deterministic split-K reduction)
__global__ __launch_bounds__(256, 8) void reduceS(
    const float* __restrict__ p, float* __restrict__ o, float scale) {
    const long NT = (long)BB * CC * CC / 4;  // float4 count per partial
    long i = (long)blockIdx.x * 256 + threadIdx.x;
    if (i >= NT) return;
    const float4* p4 = reinterpret_cast<const float4*>(p);
    float4 a = p4[i], b = p4[i + NT], c = p4[i + 2 * NT], d = p4[i + 3 * NT];
    float4 rr;
    rr.x = (a.x + b.x + c.x + d.x) * scale;
    rr.y = (a.y + b.y + c.y + d.y) * scale;
    rr.z = (a.z + b.z + c.z + d.z) * scale;
    rr.w = (a.w + b.w + c.w + d.w) * scale;
    reinterpret_cast<float4*>(o)[i] = rr;
}

extern "C" void kernel_launch(void* const* d_in, const int* in_sizes, int n_in,
                              void* d_out, int out_size) {
    const float* x  = (const float*)d_in[0];
    const float* wA = (const float*)d_in[1];
    const float* bA = (const float*)d_in[2];
    const float* wB = (const float*)d_in[3];
    const float* bB = (const float*)d_in[4];
    const float* wV = (const float*)d_in[5];
    const float* bV = (const float*)d_in[6];
    float* out = (float*)d_out;

    float *logits, *Sp, *S, *gd;
    cudaGetSymbolAddress((void**)&logits, g_logits);
    cudaGetSymbolAddress((void**)&Sp, g_Sp);
    cudaGetSymbolAddress((void**)&S, g_S);
    cudaGetSymbolAddress((void**)&gd, g_gd);

    const long sX  = (long)CC * HW_;        // x batch stride
    const long sL  = (long)2 * CC * HW_;    // logits batch stride
    const long sCC = (long)CC * CC;
    const long sSp = (long)BB * CC * CC;    // split-partial stride
    const float invHW = 1.0f / (float)HW_;
    dim3 blk(256);

    // 1) B logits: wB @ x + bB -> logits[b, 0:512, :]
    gemm_tf32<false, false, 1><<<dim3(HW_ / BN, CC / BM, BB), blk>>>(
        wB, x, logits, CC, HW_, CC, 0, sX, sL, 0, bB, 1, 1.f, 1.f);
    // 2) V logits -> logits[b, 512:1024, :]
    gemm_tf32<false, false, 1><<<dim3(HW_ / BN, CC / BM, BB), blk>>>(
        wV, x, logits + (long)CC * HW_, CC, HW_, CC, 0, sX, sL, 0, bV, 1, 1.f, 1.f);
    // 3) softmax over all 8*1024 rows, in place
    softmax_rows<<<BB * 2 * CC, blk>>>(logits);
    // 4) S partials = Bm @ x^T, split-K=4 (K=4096 -> 4x1024), 256 CTAs
    gemm_tf32<false, true, NSPLIT4><<<dim3(CC / BN, CC / BM, BB * NSPLIT4), blk>>>(
        logits, x, Sp, CC, CC, HW_, sL, sX, sCC, sSp, nullptr, 0, 1.f, 1.f);
    //    reduce partials -> S (with 1/HW folded in)
    reduceS<<<(unsigned)((sSp / 4 + 255) / 256), blk>>>(Sp, S, invHW);
    // 5) gd = S @ wA^T + bA/HW
    gemm_tf32<false, true, 1><<<dim3(CC / BN, CC / BM, BB), blk>>>(
        S, wA, gd, CC, CC, CC, sCC, 0, sCC, 0, bA, 2, 1.f, invHW);
    // 6) out = gd^T @ av
    gemm_tf32<true, false, 1><<<dim3(HW_ / BN, CC / BM, BB), blk>>>(
        gd, logits + (long)CC * HW_, out, CC, HW_, CC, sCC, sL, (long)CC * HW_, 0,
        nullptr, 0, 1.f, 1.f);
}

// round 13
// speedup vs baseline: 1.3304x; 1.3304x over previous
#include <cuda_runtime.h>
#include <cuda_fp16.h>
#include <cstdint>

// ---------------------------------------------------------------------------
// DoubleAttention, restructured (A-conv algebraically eliminated):
//   L = [wB;wV] x + [bB;bV]     (2x GEMM  M=512, N=4096, K=512, per batch)
//   Bm, av = softmax_rows(L)
//   S  = Bm @ x^T               (GEMM M=512, N=512, K=4096; split-K=4 + reduce)
//   gdT = wA @ S^T + bA         (GEMM M=512, N=512, K=512; O(1) values)
//   out= (gdT @ av) * 1/HW      (GEMM M=512, N=4096, K=512; 1/HW folded at output
//                                so every fp16 GEMM input stays O(1))
// fp16 mma.sync m16n8k16, f32 accumulate. fp16 has the SAME 10-bit mantissa as
// tf32 -> same rounding error, 2x FLOP/instruction, half the LDS per FLOP.
// SMEM holds half2 k-pairs, k-major, stride 136, swizzle ((kp>>2)&1)<<3:
// fragment loads, STS.128 stores and transpose STS.32 all bank-conflict-free.
// A operand is ALWAYS row-major [M,K] (step 5 emits gd transposed).
// ---------------------------------------------------------------------------

#define BB   8
#define CC   512
#define HW_  4096

#define BM 128
#define BN 128
#define BK 16          // one m16n8k16 slice per tile
#define KP 8           // BK/2 half2 k-pairs
#define PAD 8          // row stride 136 words = 8 mod 32

#define NSPLIT4 4

// Scratch (__device__ globals; allocation is forbidden)
__device__ float g_logits[BB * 2 * CC * HW_];          // 134MB
__device__ float g_Sp[NSPLIT4 * BB * CC * CC];         // 33.5MB split-K partials
__device__ float g_S [BB * CC * CC];                   // 8MB
__device__ float g_gd[BB * CC * CC];                   // 8MB (holds gd^T)

// pack2(even, odd): low half = even-k element (PTX: first source -> upper half)
__device__ __forceinline__ uint32_t pack2(float e, float o) {
    uint32_t u;
    asm("cvt.rn.f16x2.f32 %0, %1, %2;" : "=r"(u) : "f"(o), "f"(e));
    return u;
}

__device__ __forceinline__ void mma16(float* c, const uint32_t* a, const uint32_t* b) {
    asm volatile(
        "mma.sync.aligned.m16n8k16.row.col.f32.f16.f16.f32 "
        "{%0,%1,%2,%3},{%4,%5,%6,%7},{%8,%9},{%0,%1,%2,%3};"
        : "+f"(c[0]), "+f"(c[1]), "+f"(c[2]), "+f"(c[3])
        : "r"(a[0]), "r"(a[1]), "r"(a[2]), "r"(a[3]), "r"(b[0]), "r"(b[1]));
}

// Swizzle: inject kp bit 2 into column bank bit 3 (16B-aligned -> STS.128 safe).
__device__ __forceinline__ int swz(int col, int kp) {
    return col ^ (((kp >> 2) & 1) << 3);
}

// D[m,n] = scale * sum_k A[m,k]*B'[n,k]  (+ biasScale*bias[row or col])
// A is ALWAYS [M,K] row-major. TB: B stored [N,K] row-major; else [K,N].
// NSPLIT: split-K factor; partial sp is written at D + sp*sSplit.
template <bool TB, int NSPLIT>
__global__ __launch_bounds__(128, 2) void gemm_f16(
    const float* __restrict__ Abase, const float* __restrict__ Bbase,
    float* __restrict__ Dbase, int N, int K,
    long sA, long sB, long sD, long sSplit,
    const float* __restrict__ bias, int biasMode, float scale, float biasScale)
{
    // k-pair-major swizzled tiles of half2 (8 kp rows x 128 cols).
    __shared__ uint32_t As[2][KP][BM + PAD];   // 4.35KB each buf pair
    __shared__ uint32_t Bs[2][KP][BN + PAD];

    const int bz    = blockIdx.z;
    const int batch = bz / NSPLIT;
    const int sp    = bz % NSPLIT;
    const int Kl    = K / NSPLIT;
    const int koff  = sp * Kl;

    const float* A  = Abase + (long)batch * sA;
    const float* Bp = Bbase + (long)batch * sB;
    float* D        = Dbase + (long)batch * sD + (long)sp * sSplit;

    const int bm   = blockIdx.y * BM;
    const int bn   = blockIdx.x * BN;
    const int tid  = threadIdx.x;
    const int lane = tid & 31;
    const int warp = tid >> 5;
    const int m0   = (warp >> 1) * 64;  // 2 warps along M
    const int n0   = (warp & 1) * 64;   // 2 warps along N
    const int r    = lane >> 2;         // 0..7
    const int cg   = lane & 3;          // 0..3

    float acc[4][8][4];
#pragma unroll
    for (int i = 0; i < 4; i++)
#pragma unroll
        for (int j = 0; j < 8; j++)
#pragma unroll
            for (int k = 0; k < 4; k++) acc[i][j][k] = 0.f;

    float4 pa[4], pb[4];

    auto loadA = [&](int k0) {   // A row-major [M,K]: 128x16 = 512 float4
#pragma unroll
        for (int i = 0; i < 4; i++) {
            int idx = tid + i * 128;
            int m = idx >> 2, kq = idx & 3;
            pa[i] = *reinterpret_cast<const float4*>(&A[(long)(bm + m) * K + k0 + kq * 4]);
        }
    };
    auto storeA = [&](uint32_t (*Asb)[BM + PAD]) {
#pragma unroll
        for (int i = 0; i < 4; i++) {
            int idx = tid + i * 128;
            int m = idx >> 2, kq = idx & 3;
            int kp0 = kq * 2;
            // banks: 16(kq&1) + (m ^ 8(kq>>1)) -> offsets {0,16,8,24}+m: all 32
            Asb[kp0    ][swz(m, kp0)] = pack2(pa[i].x, pa[i].y);
            Asb[kp0 + 1][swz(m, kp0)] = pack2(pa[i].z, pa[i].w);
        }
    };
    auto loadB = [&](int k0) {
        if (!TB) {   // B [K,N]: pair rows k=2kp,2kp+1; 8 kp x 32 n4 = 256 units
#pragma unroll
            for (int i = 0; i < 2; i++) {
                int idx = tid + i * 128;
                int n4 = idx & 31, kp = idx >> 5;
                const float* q = Bp + (long)(k0 + 2 * kp) * N + bn + n4 * 4;
                pb[2 * i]     = *reinterpret_cast<const float4*>(q);
                pb[2 * i + 1] = *reinterpret_cast<const float4*>(q + N);
            }
        } else {     // B [N,K] row-major
#pragma unroll
            for (int i = 0; i < 4; i++) {
                int idx = tid + i * 128;
                int n = idx >> 2, kq = idx & 3;
                pb[i] = *reinterpret_cast<const float4*>(&Bp[(long)(bn + n) * K + k0 + kq * 4]);
            }
        }
    };
    auto storeB = [&](uint32_t (*Bsb)[BN + PAD]) {
        if (!TB) {   // one STS.128 per (kp, n4); per-warp kp const, n4=lane: no conflicts
#pragma unroll
            for (int i = 0; i < 2; i++) {
                int idx = tid + i * 128;
                int n4 = idx & 31, kp = idx >> 5;
                float4 v0 = pb[2 * i], v1 = pb[2 * i + 1];
                uint4 q = make_uint4(pack2(v0.x, v1.x), pack2(v0.y, v1.y),
                                     pack2(v0.z, v1.z), pack2(v0.w, v1.w));
                *reinterpret_cast<uint4*>(&Bsb[kp][swz(n4 * 4, kp)]) = q;
            }
        } else {     // transpose path, same conflict-free pattern as storeA
#pragma unroll
            for (int i = 0; i < 4; i++) {
                int idx = tid + i * 128;
                int n = idx >> 2, kq = idx & 3;
                int kp0 = kq * 2;
                Bsb[kp0    ][swz(n, kp0)] = pack2(pb[i].x, pb[i].y);
                Bsb[kp0 + 1][swz(n, kp0)] = pack2(pb[i].z, pb[i].w);
            }
        }
    };

    // One K=16 mma slice per tile; compile-time buffer => [R+imm] addressing.
    auto compute = [&](const uint32_t (*Asb)[BM + PAD],
                       const uint32_t (*Bsb)[BN + PAD]) {
        uint32_t afr[4][4], bfr[8][2];
#pragma unroll
        for (int mt = 0; mt < 4; mt++) {
            int mrow = m0 + mt * 16;
            afr[mt][0] = Asb[cg    ][mrow + r];          // kp=cg:   X=0
            afr[mt][1] = Asb[cg    ][mrow + r + 8];
            afr[mt][2] = Asb[cg + 4][(mrow + r) ^ 8];    // kp=cg+4: X=8
            afr[mt][3] = Asb[cg + 4][(mrow + r + 8) ^ 8];
        }
#pragma unroll
        for (int nt = 0; nt < 8; nt++) {
            int ncol = n0 + nt * 8 + r;
            bfr[nt][0] = Bsb[cg    ][ncol];
            bfr[nt][1] = Bsb[cg + 4][ncol ^ 8];
        }
#pragma unroll
        for (int mt = 0; mt < 4; mt++)
#pragma unroll
            for (int nt = 0; nt < 8; nt++) mma16(acc[mt][nt], afr[mt], bfr[nt]);
    };

    const int nk = Kl / BK;   // 32 or 64: always even
    loadA(koff); loadB(koff);
    storeA(As[0]); storeB(Bs[0]);
    __syncthreads();

    for (int kt = 0; kt < nk; kt += 2) {
        loadA(koff + (kt + 1) * BK); loadB(koff + (kt + 1) * BK);
        compute(As[0], Bs[0]);
        storeA(As[1]); storeB(Bs[1]);
        __syncthreads();
        const bool more = (kt + 2 < nk);
        if (more) { loadA(koff + (kt + 2) * BK); loadB(koff + (kt + 2) * BK); }
        compute(As[1], Bs[1]);
        if (more) {
            storeA(As[0]); storeB(Bs[0]);
            __syncthreads();
        }
    }

    // epilogue (m16n8k16 D layout == m16n8k8: d0..d3 at (r,2cg),(r,2cg+1),(r+8,..))
#pragma unroll
    for (int mt = 0; mt < 4; mt++) {
        int row0 = bm + m0 + mt * 16 + r;
#pragma unroll
        for (int nt = 0; nt < 8; nt++) {
            int col = bn + n0 + nt * 8 + cg * 2;
            float v0 = acc[mt][nt][0] * scale;
            float v1 = acc[mt][nt][1] * scale;
            float v2 = acc[mt][nt][2] * scale;
            float v3 = acc[mt][nt][3] * scale;
            if (biasMode == 1) {
                float b0 = bias[row0] * biasScale;
                float b1 = bias[row0 + 8] * biasScale;
                v0 += b0; v1 += b0; v2 += b1; v3 += b1;
            } else if (biasMode == 2) {
                float b0 = bias[col] * biasScale;
                float b1 = bias[col + 1] * biasScale;
                v0 += b0; v1 += b1; v2 += b0; v3 += b1;
            }
            D[(long)row0 * N + col]           = v0;
            D[(long)row0 * N + col + 1]       = v1;
            D[(long)(row0 + 8) * N + col]     = v2;
            D[(long)(row0 + 8) * N + col + 1] = v3;
        }
    }
}

// In-place softmax over rows of length 4096. One CTA (256 threads) per row.
__global__ __launch_bounds__(256, 1) void softmax_rows(float* __restrict__ buf) {
    float* p = buf + (long)blockIdx.x * HW_;
    const int tid  = threadIdx.x;
    const int lane = tid & 31;
    const int warp = tid >> 5;
    __shared__ float red[8];

    float4 v[4];
    float4* p4 = reinterpret_cast<float4*>(p);
#pragma unroll
    for (int i = 0; i < 4; i++) v[i] = p4[i * 256 + tid];

    float mx = v[0].x;
#pragma unroll
    for (int i = 0; i < 4; i++) {
        mx = fmaxf(mx, v[i].x); mx = fmaxf(mx, v[i].y);
        mx = fmaxf(mx, v[i].z); mx = fmaxf(mx, v[i].w);
    }
#pragma unroll
    for (int o = 16; o; o >>= 1) mx = fmaxf(mx, __shfl_xor_sync(0xffffffffu, mx, o));
    if (lane == 0) red[warp] = mx;
    __syncthreads();
    mx = red[0];
#pragma unroll
    for (int w = 1; w < 8; w++) mx = fmaxf(mx, red[w]);
    __syncthreads();

    float s = 0.f;
#pragma unroll
    for (int i = 0; i < 4; i++) {
        v[i].x = __expf(v[i].x - mx); s += v[i].x;
        v[i].y = __expf(v[i].y - mx); s += v[i].y;
        v[i].z = __expf(v[i].z - mx); s += v[i].z;
        v[i].w = __expf(v[i].w - mx); s += v[i].w;
    }
#pragma unroll
    for (int o = 16; o; o >>= 1) s += __shfl_xor_sync(0xffffffffu, s, o);
    if (lane == 0) red[warp] = s;
    __syncthreads();
    s = 0.f;
#pragma unroll
    for (int w = 0; w < 8; w++) s += red[w];
    const float inv = 1.f / s;
#pragma unroll
    for (int i = 0; i < 4; i++) {
        v[i].x *= inv; v[i].y *= inv; v[i].z *= inv; v[i].w *= inv;
        p4[i * 256 + tid] = v[i];
    }
}

// S = (p0 + p1 + p2 + p3) * scale   (deterministic split-K reduction)
__global__ __launch_bounds__(256, 8) void reduceS(
    const float* __restrict__ p, float* __restrict__ o, float scale) {
    const long NT = (long)BB * CC * CC / 4;  // float4 count per partial
    long i = (long)blockIdx.x * 256 + threadIdx.x;
    if (i >= NT) return;
    const float4* p4 = reinterpret_cast<const float4*>(p);
    float4 a = p4[i], b = p4[i + NT], c = p4[i + 2 * NT], d = p4[i + 3 * NT];
    float4 rr;
    rr.x = (a.x + b.x + c.x + d.x) * scale;
    rr.y = (a.y + b.y + c.y + d.y) * scale;
    rr.z = (a.z + b.z + c.z + d.z) * scale;
    rr.w = (a.w + b.w + c.w + d.w) * scale;
    reinterpret_cast<float4*>(o)[i] = rr;
}

extern "C" void kernel_launch(void* const* d_in, const int* in_sizes, int n_in,
                              void* d_out, int out_size) {
    const float* x  = (const float*)d_in[0];
    const float* wA = (const float*)d_in[1];
    const float* bA = (const float*)d_in[2];
    const float* wB = (const float*)d_in[3];
    const float* bB = (const float*)d_in[4];
    const float* wV = (const float*)d_in[5];
    const float* bV = (const float*)d_in[6];
    float* out = (float*)d_out;

    float *logits, *Sp, *S, *gd;
    cudaGetSymbolAddress((void**)&logits, g_logits);
    cudaGetSymbolAddress((void**)&Sp, g_Sp);
    cudaGetSymbolAddress((void**)&S, g_S);
    cudaGetSymbolAddress((void**)&gd, g_gd);

    const long sX  = (long)CC * HW_;        // x batch stride
    const long sL  = (long)2 * CC * HW_;    // logits batch stride
    const long sCC = (long)CC * CC;
    const long sSp = (long)BB * CC * CC;    // split-partial stride
    const float invHW = 1.0f / (float)HW_;
    dim3 blk(128);
    dim3 blk256(256);

    // 1) B logits: wB @ x + bB -> logits[b, 0:512, :]   (B = x is [K,N])
    gemm_f16<false, 1><<<dim3(HW_ / BN, CC / BM, BB), blk>>>(
        wB, x, logits, HW_, CC, 0, sX, sL, 0, bB, 1, 1.f, 1.f);
    // 2) V logits -> logits[b, 512:1024, :]
    gemm_f16<false, 1><<<dim3(HW_ / BN, CC / BM, BB), blk>>>(
        wV, x, logits + (long)CC * HW_, HW_, CC, 0, sX, sL, 0, bV, 1, 1.f, 1.f);
    // 3) softmax over all 8*1024 rows, in place
    softmax_rows<<<BB * 2 * CC, blk256>>>(logits);
    // 4) S partials = Bm @ x^T, split-K=4 (K=4096 -> 4x1024)  (B = x as [N,K])
    gemm_f16<true, NSPLIT4><<<dim3(CC / BN, CC / BM, BB * NSPLIT4), blk>>>(
        logits, x, Sp, CC, HW_, sL, sX, sCC, sSp, nullptr, 0, 1.f, 1.f);
    //    reduce partials -> S UNSCALED (keeps step-5/6 fp16 inputs at O(1))
    reduceS<<<(unsigned)((sSp / 4 + 255) / 256), blk256>>>(Sp, S, 1.f);
    // 5) gdT = wA @ S^T + bA  (gd stored TRANSPOSED; B = S is [N,K]; O(1) values)
    gemm_f16<true, 1><<<dim3(CC / BN, CC / BM, BB), blk>>>(
        wA, S, gd, CC, CC, 0, sCC, sCC, 0, bA, 1, 1.f, 1.f);
    // 6) out = (gdT @ av) * 1/HW   (A = gdT row-major; B = av is [K,N])
    gemm_f16<false, 1><<<dim3(HW_ / BN, CC / BM, BB), blk>>>(
        gd, logits + (long)CC * HW_, out, HW_, CC, sCC, sL, (long)CC * HW_, 0,
        nullptr, 0, invHW, 1.f);
}